// round 15
// baseline (speedup 1.0000x reference)
#include <cuda_runtime.h>
#include <cuda_bf16.h>
#include <cuda_fp16.h>
#include <cstdint>

#define TOK   4096
#define DH    16384
#define DM    1024
#define KSEL  64
#define CMAX  192
#define CBAND 448
#define RWIN  1.5e-2f

// ---- scratch (device globals; no runtime allocation) ----
__device__ __align__(16) unsigned short g_zq[(long)TOK * DH];  // 128 MB quantized z
__device__ __align__(16) __nv_bfloat16 g_Abf[(long)TOK * DM];
__device__ __align__(16) __nv_bfloat16 g_Bbf[(long)DH * DM];   // W_enc^T bf16 (GEMM)
__device__ __align__(16) __half        g_Whi[(long)DH * DM];   // W_enc^T fp16 hi
__device__ __align__(16) __half        g_Wlo[(long)DH * DM];   // W_enc^T fp16 lo (x1024)
__device__ __align__(16) __half        g_Wd16[(long)DH * DM];  // W_dec fp16

// ============================================================
// helpers
// ============================================================
__device__ __forceinline__ uint32_t smem_u32(const void* p) {
    uint32_t a;
    asm("{ .reg .u64 t; cvta.to.shared.u64 t, %1; cvt.u32.u64 %0, t; }"
        : "=r"(a) : "l"(p));
    return a;
}
#define SWZ128(o) ((o) ^ (((o) >> 3) & 0x70))

#define CPASYNC16(dst, src) \
    asm volatile("cp.async.cg.shared.global [%0], [%1], 16;" \
                 :: "r"(dst), "l"(src) : "memory")
#define CP_COMMIT() asm volatile("cp.async.commit_group;" ::: "memory")

#define MMA16816(c, a, b0, b1) \
    asm volatile("mma.sync.aligned.m16n8k16.row.col.f32.bf16.bf16.f32 " \
        "{%0,%1,%2,%3}, {%4,%5,%6,%7}, {%8,%9}, {%0,%1,%2,%3};" \
        : "+f"((c)[0]), "+f"((c)[1]), "+f"((c)[2]), "+f"((c)[3]) \
        : "r"((a)[0]), "r"((a)[1]), "r"((a)[2]), "r"((a)[3]), "r"(b0), "r"(b1))

#define LDMATX4(r, ad) \
    asm volatile("ldmatrix.sync.aligned.m8n8.x4.shared.b16 {%0,%1,%2,%3}, [%4];" \
        : "=r"((r)[0]), "=r"((r)[1]), "=r"((r)[2]), "=r"((r)[3]) : "r"(ad))

__device__ __forceinline__ void two_sum(float a, float b, float& s, float& e) {
    s = a + b;
    float bv = s - a;
    e = (a - (s - bv)) + (b - bv);
}

// ---- near-exact ranking dot: TwoProd on fp16-hi + scaled fp16-lo ----
__device__ __forceinline__ double dfh_dot_warp(const float* __restrict__ x,
                                               const __half* __restrict__ whi,
                                               const __half* __restrict__ wlo,
                                               int lane) {
    float shi = 0.f, slo = 0.f, lacc = 0.f;
#pragma unroll
    for (int i = 0; i < 16; i++) {
        const int k = 2 * (lane + 32 * i);
        const float2 hf = __half22float2(*(const __half2*)&whi[k]);
        const float2 lf = __half22float2(*(const __half2*)&wlo[k]);
        const float x0 = x[k], x1 = x[k + 1];
        float p, pe, s, e;
        p = x0 * hf.x; pe = fmaf(x0, hf.x, -p);
        two_sum(shi, p, s, e); slo += e + pe; shi = s;
        p = x1 * hf.y; pe = fmaf(x1, hf.y, -p);
        two_sum(shi, p, s, e); slo += e + pe; shi = s;
        lacc = fmaf(x0, lf.x, lacc);
        lacc = fmaf(x1, lf.y, lacc);
    }
#pragma unroll
    for (int off = 16; off; off >>= 1) {
        float h2 = __shfl_down_sync(0xFFFFFFFFu, shi, off);
        float l2 = __shfl_down_sync(0xFFFFFFFFu, slo, off);
        float a2 = __shfl_down_sync(0xFFFFFFFFu, lacc, off);
        float s, e;
        two_sum(shi, h2, s, e);
        slo = slo + l2 + e;
        shi = s;
        lacc += a2;
    }
    return (double)shi + (double)slo + (double)lacc * 0.0009765625;   // lane 0
}

// ---- fp32 dot over fp16-hi weights (value recompute) ----
__device__ __forceinline__ float dot16_warp(const float* __restrict__ x,
                                            const __half* __restrict__ w,
                                            int lane) {
    float acc = 0.f;
#pragma unroll
    for (int i = 0; i < 16; i++) {
        const int k = 2 * (lane + 32 * i);
        const float2 f = __half22float2(*(const __half2*)&w[k]);
        acc = fmaf(x[k],     f.x, acc);
        acc = fmaf(x[k + 1], f.y, acc);
    }
#pragma unroll
    for (int off = 16; off; off >>= 1)
        acc += __shfl_down_sync(0xFFFFFFFFu, acc, off);
    return acc;                          // lane 0
}

// ============================================================
// Prepass 1: x -> bf16
// ============================================================
__global__ __launch_bounds__(256) void split_x_kernel(const float* __restrict__ x)
{
    long i = (long)blockIdx.x * 256 + threadIdx.x;
    float4 v = ((const float4*)x)[i];
    __nv_bfloat16 h[4];
    h[0] = __float2bfloat16(v.x); h[1] = __float2bfloat16(v.y);
    h[2] = __float2bfloat16(v.z); h[3] = __float2bfloat16(v.w);
    ((uint2*)g_Abf)[i] = *(uint2*)h;
}

// ============================================================
// Prepass 2: transpose W_enc [DM,DH] -> [DH,DM] bf16 + fp16 hi/lo
// ============================================================
__global__ __launch_bounds__(256) void split_w_kernel(const float* __restrict__ W)
{
    __shared__ float s[32][33];
    const int n0 = blockIdx.x * 32, k0 = blockIdx.y * 32;
    const int tx = threadIdx.x, ty = threadIdx.y;
#pragma unroll
    for (int i = 0; i < 4; i++)
        s[ty + 8 * i][tx] = W[(long)(k0 + ty + 8 * i) * DH + n0 + tx];
    __syncthreads();
#pragma unroll
    for (int i = 0; i < 4; i++) {
        const int n = n0 + ty + 8 * i, k = k0 + tx;
        const float f = s[tx][ty + 8 * i];
        const __half h = __float2half(f);
        const float l32 = (f - __half2float(h)) * 1024.f;
        g_Whi[(long)n * DM + k] = h;
        g_Wlo[(long)n * DM + k] = __float2half(l32);
        g_Bbf[(long)n * DM + k] = __float2bfloat16(f);
    }
}

// ============================================================
// Prepass 3: W_dec fp32 -> fp16 (same layout)
// ============================================================
__global__ __launch_bounds__(256) void split_wd_kernel(const float* __restrict__ Wd)
{
    long i = (long)blockIdx.x * 256 + threadIdx.x;   // float4 index
    float4 v = ((const float4*)Wd)[i];
    __half h[4];
    h[0] = __float2half(v.x); h[1] = __float2half(v.y);
    h[2] = __float2half(v.z); h[3] = __float2half(v.w);
    ((uint2*)g_Wd16)[i] = *(uint2*)h;
}

// ============================================================
// Encode GEMM: bf16 HMMA, 4-stage pipeline with loads issued
// BEFORE compute each iteration (deep cp.async cover).
// ============================================================
#define BM 128
#define BN 256
#define BKG 64
#define ASTG 16384
#define STAGE 49152
#define NSTG 4
#define SMEM_DYN (NSTG * STAGE)     // 196608

__device__ __forceinline__ unsigned short q16z(float z) {
    z = fmaxf(z, 0.f);
    return (unsigned short)(__float_as_uint(z) >> 16);
}

__global__ __launch_bounds__(256, 1) void encode_mma_kernel(const float* __restrict__ bias)
{
    extern __shared__ __align__(1024) char smem[];
    const uint32_t smb = smem_u32(smem);
    const int tid = threadIdx.x, lane = tid & 31, wid = tid >> 5;
    const int wm = wid >> 2, wn = wid & 3;
    const int m0 = blockIdx.y * BM, n0 = blockIdx.x * BN;

    int arow[4], bro[8];
    uint32_t asw[4], bsw[8];
    long asrc[4], bsrc[8];
#pragma unroll
    for (int i = 0; i < 4; i++) {
        int c = tid + 256 * i;
        arow[i] = c >> 3;
        int ch = c & 7;
        asw[i] = SWZ128((uint32_t)(arow[i] * 128 + ch * 16));
        asrc[i] = (long)(m0 + arow[i]) * DM + ch * 8;
    }
#pragma unroll
    for (int i = 0; i < 8; i++) {
        int c = tid + 256 * i;
        bro[i] = c >> 3;
        int ch = c & 7;
        bsw[i] = SWZ128((uint32_t)(bro[i] * 128 + ch * 16));
        bsrc[i] = (long)(n0 + bro[i]) * DM + ch * 8;
    }

    const int rowA = wm * 64 + (lane & 7) + ((lane >> 3) & 1) * 8;
    const int kbA  = ((lane >> 4) & 1) * 16;
    const int rowB = wn * 64 + (lane & 7) + ((lane >> 4) & 1) * 8;
    const int kbB  = ((lane >> 3) & 1) * 16;

    float acc[4][8][4];
#pragma unroll
    for (int m = 0; m < 4; m++)
#pragma unroll
        for (int n = 0; n < 8; n++)
#pragma unroll
            for (int r = 0; r < 4; r++) acc[m][n][r] = 0.f;

    auto issue = [&](int k0, int s) {
        const uint32_t As = smb + s * STAGE;
        const uint32_t Bs = As + ASTG;
#pragma unroll
        for (int i = 0; i < 4; i++)
            CPASYNC16(As + asw[i], (const char*)(g_Abf + asrc[i] + k0));
#pragma unroll
        for (int i = 0; i < 8; i++)
            CPASYNC16(Bs + bsw[i], (const char*)(g_Bbf + bsrc[i] + k0));
    };

    auto compute = [&](int s) {
        const uint32_t As = smb + s * STAGE;
        const uint32_t Bs = As + ASTG;
#pragma unroll
        for (int ks = 0; ks < 4; ks++) {
            uint32_t a[4][4], bq[4][4];
#pragma unroll
            for (int mt = 0; mt < 4; mt++) {
                uint32_t off = (uint32_t)((rowA + mt * 16) * 128 + ks * 32 + kbA);
                LDMATX4(a[mt], As + SWZ128(off));
            }
#pragma unroll
            for (int j = 0; j < 4; j++) {
                uint32_t off = (uint32_t)((rowB + j * 16) * 128 + ks * 32 + kbB);
                LDMATX4(bq[j], Bs + SWZ128(off));
            }
#pragma unroll
            for (int mt = 0; mt < 4; mt++)
#pragma unroll
                for (int j = 0; j < 4; j++) {
                    MMA16816(acc[mt][2 * j],     a[mt], bq[j][0], bq[j][1]);
                    MMA16816(acc[mt][2 * j + 1], a[mt], bq[j][2], bq[j][3]);
                }
        }
    };

    // ---- 3-deep prologue ----
    issue(0,   0); CP_COMMIT();
    issue(64,  1); CP_COMMIT();
    issue(128, 2); CP_COMMIT();

    const int NIT = DM / BKG;   // 16
    for (int i = 0; i < NIT; i++) {
        // graduated wait: keep up to 2 stages in flight
        if (i < NIT - 2)       asm volatile("cp.async.wait_group 2;" ::: "memory");
        else if (i == NIT - 2) asm volatile("cp.async.wait_group 1;" ::: "memory");
        else                   asm volatile("cp.async.wait_group 0;" ::: "memory");
        __syncthreads();
        // issue next stage BEFORE compute -> ~3 compute phases of cover
        if (i + 3 < NIT) {
            issue((i + 3) * BKG, (i + 3) & 3);
            CP_COMMIT();
        }
        compute(i & 3);
    }

    // ---- epilogue: bias + ReLU -> quantized 16-bit store ----
    const int r0  = m0 + wm * 64 + (lane >> 2);
    const int c0  = n0 + wn * 64 + (lane & 3) * 2;
#pragma unroll
    for (int nt = 0; nt < 8; nt++) {
        const int col = c0 + nt * 8;
        const float2 bv = *(const float2*)&bias[col];
#pragma unroll
        for (int mt = 0; mt < 4; mt++) {
            const int r = r0 + mt * 16;
            ushort2 o0, o1;
            o0.x = q16z(acc[mt][nt][0] + bv.x);
            o0.y = q16z(acc[mt][nt][1] + bv.y);
            o1.x = q16z(acc[mt][nt][2] + bv.x);
            o1.y = q16z(acc[mt][nt][3] + bv.y);
            *(ushort2*)&g_zq[(long)r * DH + col]       = o0;
            *(ushort2*)&g_zq[(long)(r + 8) * DH + col] = o1;
        }
    }
}

// ============================================================
// Fused TopK + decode (R14, unchanged).
// ============================================================
__global__ __launch_bounds__(256) void topk_decode_kernel(
    const float* __restrict__ X,
    const float* __restrict__ benc,
    const float* __restrict__ bd,
    float* __restrict__ Y)
{
    extern __shared__ unsigned smq[];   // 32 KB: DH 16-bit values
    __shared__ float  s_x[DM];
    __shared__ unsigned s_key[512];
    __shared__ int    s_cidx[CMAX];
    __shared__ double s_cval[CMAX];
    __shared__ int    s_selidx[KSEL];
    __shared__ float  s_selval[KSEL];
    __shared__ float  s_p1[8], s_p2[8];
    __shared__ int    s_red, s_na, s_nc, s_cnt;
    __shared__ float  s_t;

    const int row = blockIdx.x;
    const int tid = threadIdx.x;
    const int wid = tid >> 5, lane = tid & 31;
    const float* xr = X + (long)row * DM;

    for (int k = tid; k < DM; k += 256) s_x[k] = xr[k];

    // ---- stage quantized row + moments ----
    {
        const uint4* zq4 = (const uint4*)(g_zq + (long)row * DH);
        uint4* s4 = (uint4*)smq;
        float sum = 0.f, ss = 0.f;
#pragma unroll 2
        for (int i = tid; i < DH / 8; i += 256) {
            uint4 u = zq4[i];
            s4[i] = u;
            const unsigned ws[4] = {u.x, u.y, u.z, u.w};
#pragma unroll
            for (int j = 0; j < 4; j++) {
                float a = __uint_as_float(ws[j] << 16);
                float b = __uint_as_float(ws[j] & 0xFFFF0000u);
                sum += a + b;
                ss  += a * a + b * b;
            }
        }
#pragma unroll
        for (int o = 16; o; o >>= 1) {
            sum += __shfl_xor_sync(0xFFFFFFFFu, sum, o);
            ss  += __shfl_xor_sync(0xFFFFFFFFu, ss,  o);
        }
        if (lane == 0) { s_p1[wid] = sum; s_p2[wid] = ss; }
        __syncthreads();
        if (tid == 0) {
            float S = 0.f, S2 = 0.f;
#pragma unroll
            for (int w = 0; w < 8; w++) { S += s_p1[w]; S2 += s_p2[w]; }
            const float mu = S / DH;
            const float var = fmaxf(S2 / DH - mu * mu, 0.f);
            s_t = mu + 3.0f * sqrtf(var);
        }
        __syncthreads();
    }

    auto count_ge = [&](unsigned q16) -> int {
        if (tid == 0) s_red = 0;
        __syncthreads();
        int cc = 0;
#pragma unroll 8
        for (int i = 0; i < DH / 512; i++) {
            const unsigned u = smq[i * 256 + tid];
            cc += ((u & 0xFFFFu) >= q16) ? 1 : 0;
            cc += ((u >> 16)     >= q16) ? 1 : 0;
        }
#pragma unroll
        for (int o = 16; o; o >>= 1) cc += __shfl_xor_sync(0xFFFFFFFFu, cc, o);
        if (lane == 0) atomicAdd(&s_red, cc);
        __syncthreads();
        const int c = s_red;
        __syncthreads();
        return c;
    };

    // ---- moment-guided threshold iteration ----
    float t = s_t;
    unsigned tb16 = 0;
    bool ok = false;
    for (int it = 0; it < 24; ++it) {
        if (!(t > 4.f * RWIN)) break;
        const unsigned q16 = __float_as_uint(t) >> 16;
        const int c = count_ge(q16);
        if (c >= KSEL && c <= CBAND) { tb16 = q16; ok = true; break; }
        t = (c < KSEL) ? t * 0.85f : t * 1.12f;
    }

    bool fast = false;

    if (ok) {
        if (tid == 0) s_nc = 0;
        __syncthreads();
        for (int i = 0; i < DH / 512; i++) {
            const unsigned u = smq[i * 256 + tid];
            const unsigned v0 = u & 0xFFFFu, v1 = u >> 16;
            if (v0 >= tb16) { int p = atomicAdd(&s_nc, 1); s_key[p] = v0; }
            if (v1 >= tb16) { int p = atomicAdd(&s_nc, 1); s_key[p] = v1; }
        }
        __syncthreads();
        const int cc0 = s_nc;
        for (int p = tid; p < 512; p += 256)
            if (p >= cc0) s_key[p] = 0u;
        __syncthreads();

        // bitonic sort 512 values, descending
        for (int k = 2; k <= 512; k <<= 1) {
            for (int j = k >> 1; j; j >>= 1) {
#pragma unroll
                for (int rr = 0; rr < 2; rr++) {
                    const int i2 = tid + 256 * rr;
                    const int p = i2 ^ j;
                    if (p > i2) {
                        unsigned a = s_key[i2], b = s_key[p];
                        const bool up = ((i2 & k) == 0);
                        if (up ? (a < b) : (a > b)) { s_key[i2] = b; s_key[p] = a; }
                    }
                }
                __syncthreads();
            }
        }

        const unsigned h64 = s_key[63];
        const float tf_lo = __uint_as_float(h64 << 16);
        const float qw = __uint_as_float((h64 + 1) << 16) - tf_lo;

        if (tf_lo > 2.0f * RWIN) {
            const unsigned hib16 = __float_as_uint(tf_lo + qw + RWIN) >> 16;
            const unsigned lob16 = __float_as_uint(tf_lo - RWIN) >> 16;
            if (tid == 0) { s_na = 0; s_nc = 0; }
            __syncthreads();
            for (int i = 0; i < DH / 512; i++) {
                const unsigned u = smq[i * 256 + tid];
                const int gi0 = (i * 256 + tid) * 2;
#pragma unroll
                for (int h = 0; h < 2; h++) {
                    const unsigned v = h ? (u >> 16) : (u & 0xFFFFu);
                    const int gi = gi0 + h;
                    if (v > hib16) {
                        int p = atomicAdd(&s_na, 1);
                        s_selidx[p] = gi;
                    } else if (v >= lob16) {
                        int p = atomicAdd(&s_nc, 1);
                        if (p < CMAX) s_cidx[p] = gi;
                    }
                }
            }
            __syncthreads();
            const int cA = s_na, cC = s_nc;
            if (cC <= CMAX) {
                for (int c2 = wid; c2 < cC; c2 += 8) {
                    const int fi = s_cidx[c2];
                    double d = dfh_dot_warp(s_x, g_Whi + (long)fi * DM,
                                            g_Wlo + (long)fi * DM, lane);
                    if (lane == 0) {
                        d += (double)benc[fi];
                        s_cval[c2] = d > 0.0 ? d : 0.0;
                    }
                }
                __syncthreads();
                const int need = KSEL - cA;
                for (int c2 = tid; c2 < cC; c2 += 256) {
                    const double v = s_cval[c2];
                    const int fi = s_cidx[c2];
                    int rank = 0;
                    for (int c3 = 0; c3 < cC; c3++) {
                        const double u = s_cval[c3];
                        if (u > v || (u == v && s_cidx[c3] < fi)) rank++;
                    }
                    if (rank < need) s_selidx[cA + rank] = fi;
                }
                __syncthreads();
                for (int j = wid; j < KSEL; j += 8) {
                    const int fi = s_selidx[j];
                    float d = dot16_warp(s_x, g_Whi + (long)fi * DM, lane);
                    if (lane == 0) {
                        d += benc[fi];
                        s_selval[j] = fmaxf(d, 0.f);
                    }
                }
                if (tid == 0) s_cnt = KSEL;
                fast = true;
            }
            __syncthreads();
        }
    }

    if (!fast) {
        // ---- fallback on quantized data (degenerate rows; cold) ----
        unsigned qlo = 1u, qhi = 0x7F80u;
        if (count_ge(1u) < KSEL) {
            if (tid == 0) s_na = 0;
            __syncthreads();
            for (int i = 0; i < DH / 512; i++) {
                const unsigned u = smq[i * 256 + tid];
                const int gi0 = (i * 256 + tid) * 2;
#pragma unroll
                for (int h = 0; h < 2; h++) {
                    const unsigned v = h ? (u >> 16) : (u & 0xFFFFu);
                    if (v >= 1u) {
                        int p = atomicAdd(&s_na, 1);
                        s_selidx[p] = gi0 + h;
                    }
                }
            }
            __syncthreads();
            if (tid == 0) s_cnt = s_na;
        } else {
            while (qlo < qhi) {
                unsigned mid = qlo + ((qhi - qlo + 1) >> 1);
                if (count_ge(mid) >= KSEL) qlo = mid; else qhi = mid - 1;
            }
            const unsigned q = qlo;
            if (tid == 0) s_na = 0;
            __syncthreads();
            for (int i = 0; i < DH / 512; i++) {
                const unsigned u = smq[i * 256 + tid];
                const int gi0 = (i * 256 + tid) * 2;
#pragma unroll
                for (int h = 0; h < 2; h++) {
                    const unsigned v = h ? (u >> 16) : (u & 0xFFFFu);
                    if (v > q) {
                        int p = atomicAdd(&s_na, 1);
                        s_selidx[p] = gi0 + h;
                    }
                }
            }
            __syncthreads();
            for (int i = 0; i < DH / 512; i++) {
                const unsigned u = smq[i * 256 + tid];
                const int gi0 = (i * 256 + tid) * 2;
#pragma unroll
                for (int h = 0; h < 2; h++) {
                    const unsigned v = h ? (u >> 16) : (u & 0xFFFFu);
                    if (v == q) {
                        int p = atomicAdd(&s_na, 1);
                        if (p < KSEL) s_selidx[p] = gi0 + h;
                    }
                }
            }
            __syncthreads();
            if (tid == 0) s_cnt = KSEL;
        }
        __syncthreads();
        const int scnt = s_cnt;
        for (int j = wid; j < scnt; j += 8) {
            const int fi = s_selidx[j];
            float d = dot16_warp(s_x, g_Whi + (long)fi * DM, lane);
            if (lane == 0) {
                d += benc[fi];
                s_selval[j] = fmaxf(d, 0.f);
            }
        }
    }

    // ---- fused decode (fp16 W_dec) ----
    __syncthreads();
    const int cnt = s_cnt;
    float4 acc = ((const float4*)bd)[tid];
#pragma unroll 4
    for (int j = 0; j < cnt; j++) {
        const float v = s_selval[j];
        const __half2* wrow = (const __half2*)(g_Wd16 + (long)s_selidx[j] * DM);
        const float2 f0 = __half22float2(wrow[tid * 2]);
        const float2 f1 = __half22float2(wrow[tid * 2 + 1]);
        acc.x = fmaf(v, f0.x, acc.x);
        acc.y = fmaf(v, f0.y, acc.y);
        acc.z = fmaf(v, f1.x, acc.z);
        acc.w = fmaf(v, f1.y, acc.w);
    }
    ((float4*)Y)[(long)row * (DM / 4) + tid] = acc;
}

// ============================================================
extern "C" void kernel_launch(void* const* d_in, const int* in_sizes, int n_in,
                              void* d_out, int out_size)
{
    const float* x     = (const float*)d_in[0];
    const float* W_enc = (const float*)d_in[1];
    const float* b_enc = (const float*)d_in[2];
    const float* W_dec = (const float*)d_in[3];
    const float* b_dec = (const float*)d_in[4];
    float* y = (float*)d_out;

    split_x_kernel<<<(TOK * DM) / (256 * 4), 256>>>(x);
    split_w_kernel<<<dim3(DH / 32, DM / 32), dim3(32, 8)>>>(W_enc);
    split_wd_kernel<<<((long)DH * DM) / (256 * 4), 256>>>(W_dec);

    cudaFuncSetAttribute(encode_mma_kernel,
                         cudaFuncAttributeMaxDynamicSharedMemorySize, SMEM_DYN);
    dim3 ge(DH / BN, TOK / BM);   // (64, 32)
    encode_mma_kernel<<<ge, 256, SMEM_DYN>>>(b_enc);

    cudaFuncSetAttribute(topk_decode_kernel,
                         cudaFuncAttributeMaxDynamicSharedMemorySize, DH * 2);
    topk_decode_kernel<<<TOK, 256, DH * 2>>>(x, b_enc, b_dec, y);
}

// round 16
// speedup vs baseline: 1.0537x; 1.0537x over previous
#include <cuda_runtime.h>
#include <cuda_bf16.h>
#include <cuda_fp16.h>
#include <cstdint>

#define TOK   4096
#define DH    16384
#define DM    1024
#define KSEL  64
#define CMAX  192
#define CBAND 448
#define RWIN  1.5e-2f

// ---- scratch (device globals; no runtime allocation) ----
__device__ __align__(16) unsigned short g_zq[(long)TOK * DH];  // 128 MB quantized z
__device__ __align__(16) __nv_bfloat16 g_Abf[(long)TOK * DM];
__device__ __align__(16) __nv_bfloat16 g_Bbf[(long)DH * DM];   // W_enc^T bf16 (GEMM)
__device__ __align__(16) __half        g_Whi[(long)DH * DM];   // W_enc^T fp16 hi
__device__ __align__(16) __half        g_Wlo[(long)DH * DM];   // W_enc^T fp16 lo (x1024)
__device__ __align__(16) __half        g_Wd16[(long)DH * DM];  // W_dec fp16

// ============================================================
// helpers
// ============================================================
__device__ __forceinline__ uint32_t smem_u32(const void* p) {
    uint32_t a;
    asm("{ .reg .u64 t; cvta.to.shared.u64 t, %1; cvt.u32.u64 %0, t; }"
        : "=r"(a) : "l"(p));
    return a;
}
#define SWZ128(o) ((o) ^ (((o) >> 3) & 0x70))

#define CPASYNC16(dst, src) \
    asm volatile("cp.async.cg.shared.global [%0], [%1], 16;" \
                 :: "r"(dst), "l"(src) : "memory")
#define CP_COMMIT() asm volatile("cp.async.commit_group;" ::: "memory")

#define MMA16816(c, a, b0, b1) \
    asm volatile("mma.sync.aligned.m16n8k16.row.col.f32.bf16.bf16.f32 " \
        "{%0,%1,%2,%3}, {%4,%5,%6,%7}, {%8,%9}, {%0,%1,%2,%3};" \
        : "+f"((c)[0]), "+f"((c)[1]), "+f"((c)[2]), "+f"((c)[3]) \
        : "r"((a)[0]), "r"((a)[1]), "r"((a)[2]), "r"((a)[3]), "r"(b0), "r"(b1))

#define LDMATX4(r, ad) \
    asm volatile("ldmatrix.sync.aligned.m8n8.x4.shared.b16 {%0,%1,%2,%3}, [%4];" \
        : "=r"((r)[0]), "=r"((r)[1]), "=r"((r)[2]), "=r"((r)[3]) : "r"(ad))

__device__ __forceinline__ void two_sum(float a, float b, float& s, float& e) {
    s = a + b;
    float bv = s - a;
    e = (a - (s - bv)) + (b - bv);
}

// ---- near-exact ranking dot: TwoProd on fp16-hi + scaled fp16-lo ----
__device__ __forceinline__ double dfh_dot_warp(const float* __restrict__ x,
                                               const __half* __restrict__ whi,
                                               const __half* __restrict__ wlo,
                                               int lane) {
    float shi = 0.f, slo = 0.f, lacc = 0.f;
#pragma unroll
    for (int i = 0; i < 16; i++) {
        const int k = 2 * (lane + 32 * i);
        const float2 hf = __half22float2(*(const __half2*)&whi[k]);
        const float2 lf = __half22float2(*(const __half2*)&wlo[k]);
        const float x0 = x[k], x1 = x[k + 1];
        float p, pe, s, e;
        p = x0 * hf.x; pe = fmaf(x0, hf.x, -p);
        two_sum(shi, p, s, e); slo += e + pe; shi = s;
        p = x1 * hf.y; pe = fmaf(x1, hf.y, -p);
        two_sum(shi, p, s, e); slo += e + pe; shi = s;
        lacc = fmaf(x0, lf.x, lacc);
        lacc = fmaf(x1, lf.y, lacc);
    }
#pragma unroll
    for (int off = 16; off; off >>= 1) {
        float h2 = __shfl_down_sync(0xFFFFFFFFu, shi, off);
        float l2 = __shfl_down_sync(0xFFFFFFFFu, slo, off);
        float a2 = __shfl_down_sync(0xFFFFFFFFu, lacc, off);
        float s, e;
        two_sum(shi, h2, s, e);
        slo = slo + l2 + e;
        shi = s;
        lacc += a2;
    }
    return (double)shi + (double)slo + (double)lacc * 0.0009765625;   // lane 0
}

// ---- fp32 dot over fp16-hi weights (value recompute) ----
__device__ __forceinline__ float dot16_warp(const float* __restrict__ x,
                                            const __half* __restrict__ w,
                                            int lane) {
    float acc = 0.f;
#pragma unroll
    for (int i = 0; i < 16; i++) {
        const int k = 2 * (lane + 32 * i);
        const float2 f = __half22float2(*(const __half2*)&w[k]);
        acc = fmaf(x[k],     f.x, acc);
        acc = fmaf(x[k + 1], f.y, acc);
    }
#pragma unroll
    for (int off = 16; off; off >>= 1)
        acc += __shfl_down_sync(0xFFFFFFFFu, acc, off);
    return acc;                          // lane 0
}

// ============================================================
// Prepass 1: x -> bf16
// ============================================================
__global__ __launch_bounds__(256) void split_x_kernel(const float* __restrict__ x)
{
    long i = (long)blockIdx.x * 256 + threadIdx.x;
    float4 v = ((const float4*)x)[i];
    __nv_bfloat16 h[4];
    h[0] = __float2bfloat16(v.x); h[1] = __float2bfloat16(v.y);
    h[2] = __float2bfloat16(v.z); h[3] = __float2bfloat16(v.w);
    ((uint2*)g_Abf)[i] = *(uint2*)h;
}

// ============================================================
// Prepass 2: transpose W_enc [DM,DH] -> [DH,DM] bf16 + fp16 hi/lo
// ============================================================
__global__ __launch_bounds__(256) void split_w_kernel(const float* __restrict__ W)
{
    __shared__ float s[32][33];
    const int n0 = blockIdx.x * 32, k0 = blockIdx.y * 32;
    const int tx = threadIdx.x, ty = threadIdx.y;
#pragma unroll
    for (int i = 0; i < 4; i++)
        s[ty + 8 * i][tx] = W[(long)(k0 + ty + 8 * i) * DH + n0 + tx];
    __syncthreads();
#pragma unroll
    for (int i = 0; i < 4; i++) {
        const int n = n0 + ty + 8 * i, k = k0 + tx;
        const float f = s[tx][ty + 8 * i];
        const __half h = __float2half(f);
        const float l32 = (f - __half2float(h)) * 1024.f;
        g_Whi[(long)n * DM + k] = h;
        g_Wlo[(long)n * DM + k] = __float2half(l32);
        g_Bbf[(long)n * DM + k] = __float2bfloat16(f);
    }
}

// ============================================================
// Prepass 3: W_dec fp32 -> fp16 (same layout)
// ============================================================
__global__ __launch_bounds__(256) void split_wd_kernel(const float* __restrict__ Wd)
{
    long i = (long)blockIdx.x * 256 + threadIdx.x;   // float4 index
    float4 v = ((const float4*)Wd)[i];
    __half h[4];
    h[0] = __float2half(v.x); h[1] = __float2half(v.y);
    h[2] = __float2half(v.z); h[3] = __float2half(v.w);
    ((uint2*)g_Wd16)[i] = *(uint2*)h;
}

// ============================================================
// Encode GEMM: bf16 HMMA. 128x128 CTA tile (64x32 warp tile),
// 2 CTAs/SM via __launch_bounds__(256,2), NSTG=3 (R14 schedule).
// ============================================================
#define BM 128
#define BN 128
#define BKG 64
#define ASTG 16384
#define STAGE 32768
#define NSTG 3
#define SMEM_DYN (NSTG * STAGE)     // 98304 per CTA -> 2 CTAs/SM

__device__ __forceinline__ unsigned short q16z(float z) {
    z = fmaxf(z, 0.f);
    return (unsigned short)(__float_as_uint(z) >> 16);
}

__global__ __launch_bounds__(256, 2) void encode_mma_kernel(const float* __restrict__ bias)
{
    extern __shared__ __align__(1024) char smem[];
    const uint32_t smb = smem_u32(smem);
    const int tid = threadIdx.x, lane = tid & 31, wid = tid >> 5;
    const int wm = wid >> 2, wn = wid & 3;          // 2 x 4 warp grid
    const int m0 = blockIdx.y * BM, n0 = blockIdx.x * BN;

    // cp.async: A 1024 chunks (4/thread), B 1024 chunks (4/thread)
    int arow[4], bro[4];
    uint32_t asw[4], bsw[4];
    long asrc[4], bsrc[4];
#pragma unroll
    for (int i = 0; i < 4; i++) {
        int c = tid + 256 * i;
        arow[i] = c >> 3;
        int ch = c & 7;
        asw[i] = SWZ128((uint32_t)(arow[i] * 128 + ch * 16));
        asrc[i] = (long)(m0 + arow[i]) * DM + ch * 8;
        bro[i] = arow[i];
        bsw[i] = asw[i];
        bsrc[i] = (long)(n0 + bro[i]) * DM + ch * 8;
    }

    const int rowA = wm * 64 + (lane & 7) + ((lane >> 3) & 1) * 8;
    const int kbA  = ((lane >> 4) & 1) * 16;
    const int rowB = wn * 32 + (lane & 7) + ((lane >> 4) & 1) * 8;
    const int kbB  = ((lane >> 3) & 1) * 16;

    float acc[4][4][4];      // 4 m16 x 4 n8 x 4 regs = 64
#pragma unroll
    for (int m = 0; m < 4; m++)
#pragma unroll
        for (int n = 0; n < 4; n++)
#pragma unroll
            for (int r = 0; r < 4; r++) acc[m][n][r] = 0.f;

    auto issue = [&](int k0, int s) {
        const uint32_t As = smb + s * STAGE;
        const uint32_t Bs = As + ASTG;
#pragma unroll
        for (int i = 0; i < 4; i++)
            CPASYNC16(As + asw[i], (const char*)(g_Abf + asrc[i] + k0));
#pragma unroll
        for (int i = 0; i < 4; i++)
            CPASYNC16(Bs + bsw[i], (const char*)(g_Bbf + bsrc[i] + k0));
    };

    auto compute = [&](int s) {
        const uint32_t As = smb + s * STAGE;
        const uint32_t Bs = As + ASTG;
#pragma unroll
        for (int ks = 0; ks < 4; ks++) {
            uint32_t a[4][4], bq[2][4];
#pragma unroll
            for (int mt = 0; mt < 4; mt++) {
                uint32_t off = (uint32_t)((rowA + mt * 16) * 128 + ks * 32 + kbA);
                LDMATX4(a[mt], As + SWZ128(off));
            }
#pragma unroll
            for (int j = 0; j < 2; j++) {
                uint32_t off = (uint32_t)((rowB + j * 16) * 128 + ks * 32 + kbB);
                LDMATX4(bq[j], Bs + SWZ128(off));
            }
#pragma unroll
            for (int mt = 0; mt < 4; mt++)
#pragma unroll
                for (int j = 0; j < 2; j++) {
                    MMA16816(acc[mt][2 * j],     a[mt], bq[j][0], bq[j][1]);
                    MMA16816(acc[mt][2 * j + 1], a[mt], bq[j][2], bq[j][3]);
                }
        }
    };

    // ---- R14-proven schedule: 2-deep prologue, wait 1, issue after ----
    issue(0, 0);   CP_COMMIT();
    issue(64, 1);  CP_COMMIT();

    const int NIT = DM / BKG;   // 16
    for (int i = 0; i < NIT; i++) {
        if (i < NIT - 2) asm volatile("cp.async.wait_group 1;" ::: "memory");
        else             asm volatile("cp.async.wait_group 0;" ::: "memory");
        __syncthreads();
        compute(i % NSTG);
        if (i + 2 < NIT) {
            issue((i + 2) * BKG, (i + 2) % NSTG);
            CP_COMMIT();
        }
    }

    // ---- epilogue: bias + ReLU -> quantized 16-bit store ----
    const int r0  = m0 + wm * 64 + (lane >> 2);
    const int c0  = n0 + wn * 32 + (lane & 3) * 2;
#pragma unroll
    for (int nt = 0; nt < 4; nt++) {
        const int col = c0 + nt * 8;
        const float2 bv = *(const float2*)&bias[col];
#pragma unroll
        for (int mt = 0; mt < 4; mt++) {
            const int r = r0 + mt * 16;
            ushort2 o0, o1;
            o0.x = q16z(acc[mt][nt][0] + bv.x);
            o0.y = q16z(acc[mt][nt][1] + bv.y);
            o1.x = q16z(acc[mt][nt][2] + bv.x);
            o1.y = q16z(acc[mt][nt][3] + bv.y);
            *(ushort2*)&g_zq[(long)r * DH + col]       = o0;
            *(ushort2*)&g_zq[(long)(r + 8) * DH + col] = o1;
        }
    }
}

// ============================================================
// Fused TopK + decode (R14, unchanged).
// ============================================================
__global__ __launch_bounds__(256) void topk_decode_kernel(
    const float* __restrict__ X,
    const float* __restrict__ benc,
    const float* __restrict__ bd,
    float* __restrict__ Y)
{
    extern __shared__ unsigned smq[];   // 32 KB: DH 16-bit values
    __shared__ float  s_x[DM];
    __shared__ unsigned s_key[512];
    __shared__ int    s_cidx[CMAX];
    __shared__ double s_cval[CMAX];
    __shared__ int    s_selidx[KSEL];
    __shared__ float  s_selval[KSEL];
    __shared__ float  s_p1[8], s_p2[8];
    __shared__ int    s_red, s_na, s_nc, s_cnt;
    __shared__ float  s_t;

    const int row = blockIdx.x;
    const int tid = threadIdx.x;
    const int wid = tid >> 5, lane = tid & 31;
    const float* xr = X + (long)row * DM;

    for (int k = tid; k < DM; k += 256) s_x[k] = xr[k];

    // ---- stage quantized row + moments ----
    {
        const uint4* zq4 = (const uint4*)(g_zq + (long)row * DH);
        uint4* s4 = (uint4*)smq;
        float sum = 0.f, ss = 0.f;
#pragma unroll 2
        for (int i = tid; i < DH / 8; i += 256) {
            uint4 u = zq4[i];
            s4[i] = u;
            const unsigned ws[4] = {u.x, u.y, u.z, u.w};
#pragma unroll
            for (int j = 0; j < 4; j++) {
                float a = __uint_as_float(ws[j] << 16);
                float b = __uint_as_float(ws[j] & 0xFFFF0000u);
                sum += a + b;
                ss  += a * a + b * b;
            }
        }
#pragma unroll
        for (int o = 16; o; o >>= 1) {
            sum += __shfl_xor_sync(0xFFFFFFFFu, sum, o);
            ss  += __shfl_xor_sync(0xFFFFFFFFu, ss,  o);
        }
        if (lane == 0) { s_p1[wid] = sum; s_p2[wid] = ss; }
        __syncthreads();
        if (tid == 0) {
            float S = 0.f, S2 = 0.f;
#pragma unroll
            for (int w = 0; w < 8; w++) { S += s_p1[w]; S2 += s_p2[w]; }
            const float mu = S / DH;
            const float var = fmaxf(S2 / DH - mu * mu, 0.f);
            s_t = mu + 3.0f * sqrtf(var);
        }
        __syncthreads();
    }

    auto count_ge = [&](unsigned q16) -> int {
        if (tid == 0) s_red = 0;
        __syncthreads();
        int cc = 0;
#pragma unroll 8
        for (int i = 0; i < DH / 512; i++) {
            const unsigned u = smq[i * 256 + tid];
            cc += ((u & 0xFFFFu) >= q16) ? 1 : 0;
            cc += ((u >> 16)     >= q16) ? 1 : 0;
        }
#pragma unroll
        for (int o = 16; o; o >>= 1) cc += __shfl_xor_sync(0xFFFFFFFFu, cc, o);
        if (lane == 0) atomicAdd(&s_red, cc);
        __syncthreads();
        const int c = s_red;
        __syncthreads();
        return c;
    };

    // ---- moment-guided threshold iteration ----
    float t = s_t;
    unsigned tb16 = 0;
    bool ok = false;
    for (int it = 0; it < 24; ++it) {
        if (!(t > 4.f * RWIN)) break;
        const unsigned q16 = __float_as_uint(t) >> 16;
        const int c = count_ge(q16);
        if (c >= KSEL && c <= CBAND) { tb16 = q16; ok = true; break; }
        t = (c < KSEL) ? t * 0.85f : t * 1.12f;
    }

    bool fast = false;

    if (ok) {
        if (tid == 0) s_nc = 0;
        __syncthreads();
        for (int i = 0; i < DH / 512; i++) {
            const unsigned u = smq[i * 256 + tid];
            const unsigned v0 = u & 0xFFFFu, v1 = u >> 16;
            if (v0 >= tb16) { int p = atomicAdd(&s_nc, 1); s_key[p] = v0; }
            if (v1 >= tb16) { int p = atomicAdd(&s_nc, 1); s_key[p] = v1; }
        }
        __syncthreads();
        const int cc0 = s_nc;
        for (int p = tid; p < 512; p += 256)
            if (p >= cc0) s_key[p] = 0u;
        __syncthreads();

        // bitonic sort 512 values, descending
        for (int k = 2; k <= 512; k <<= 1) {
            for (int j = k >> 1; j; j >>= 1) {
#pragma unroll
                for (int rr = 0; rr < 2; rr++) {
                    const int i2 = tid + 256 * rr;
                    const int p = i2 ^ j;
                    if (p > i2) {
                        unsigned a = s_key[i2], b = s_key[p];
                        const bool up = ((i2 & k) == 0);
                        if (up ? (a < b) : (a > b)) { s_key[i2] = b; s_key[p] = a; }
                    }
                }
                __syncthreads();
            }
        }

        const unsigned h64 = s_key[63];
        const float tf_lo = __uint_as_float(h64 << 16);
        const float qw = __uint_as_float((h64 + 1) << 16) - tf_lo;

        if (tf_lo > 2.0f * RWIN) {
            const unsigned hib16 = __float_as_uint(tf_lo + qw + RWIN) >> 16;
            const unsigned lob16 = __float_as_uint(tf_lo - RWIN) >> 16;
            if (tid == 0) { s_na = 0; s_nc = 0; }
            __syncthreads();
            for (int i = 0; i < DH / 512; i++) {
                const unsigned u = smq[i * 256 + tid];
                const int gi0 = (i * 256 + tid) * 2;
#pragma unroll
                for (int h = 0; h < 2; h++) {
                    const unsigned v = h ? (u >> 16) : (u & 0xFFFFu);
                    const int gi = gi0 + h;
                    if (v > hib16) {
                        int p = atomicAdd(&s_na, 1);
                        s_selidx[p] = gi;
                    } else if (v >= lob16) {
                        int p = atomicAdd(&s_nc, 1);
                        if (p < CMAX) s_cidx[p] = gi;
                    }
                }
            }
            __syncthreads();
            const int cA = s_na, cC = s_nc;
            if (cC <= CMAX) {
                for (int c2 = wid; c2 < cC; c2 += 8) {
                    const int fi = s_cidx[c2];
                    double d = dfh_dot_warp(s_x, g_Whi + (long)fi * DM,
                                            g_Wlo + (long)fi * DM, lane);
                    if (lane == 0) {
                        d += (double)benc[fi];
                        s_cval[c2] = d > 0.0 ? d : 0.0;
                    }
                }
                __syncthreads();
                const int need = KSEL - cA;
                for (int c2 = tid; c2 < cC; c2 += 256) {
                    const double v = s_cval[c2];
                    const int fi = s_cidx[c2];
                    int rank = 0;
                    for (int c3 = 0; c3 < cC; c3++) {
                        const double u = s_cval[c3];
                        if (u > v || (u == v && s_cidx[c3] < fi)) rank++;
                    }
                    if (rank < need) s_selidx[cA + rank] = fi;
                }
                __syncthreads();
                for (int j = wid; j < KSEL; j += 8) {
                    const int fi = s_selidx[j];
                    float d = dot16_warp(s_x, g_Whi + (long)fi * DM, lane);
                    if (lane == 0) {
                        d += benc[fi];
                        s_selval[j] = fmaxf(d, 0.f);
                    }
                }
                if (tid == 0) s_cnt = KSEL;
                fast = true;
            }
            __syncthreads();
        }
    }

    if (!fast) {
        // ---- fallback on quantized data (degenerate rows; cold) ----
        unsigned qlo = 1u, qhi = 0x7F80u;
        if (count_ge(1u) < KSEL) {
            if (tid == 0) s_na = 0;
            __syncthreads();
            for (int i = 0; i < DH / 512; i++) {
                const unsigned u = smq[i * 256 + tid];
                const int gi0 = (i * 256 + tid) * 2;
#pragma unroll
                for (int h = 0; h < 2; h++) {
                    const unsigned v = h ? (u >> 16) : (u & 0xFFFFu);
                    if (v >= 1u) {
                        int p = atomicAdd(&s_na, 1);
                        s_selidx[p] = gi0 + h;
                    }
                }
            }
            __syncthreads();
            if (tid == 0) s_cnt = s_na;
        } else {
            while (qlo < qhi) {
                unsigned mid = qlo + ((qhi - qlo + 1) >> 1);
                if (count_ge(mid) >= KSEL) qlo = mid; else qhi = mid - 1;
            }
            const unsigned q = qlo;
            if (tid == 0) s_na = 0;
            __syncthreads();
            for (int i = 0; i < DH / 512; i++) {
                const unsigned u = smq[i * 256 + tid];
                const int gi0 = (i * 256 + tid) * 2;
#pragma unroll
                for (int h = 0; h < 2; h++) {
                    const unsigned v = h ? (u >> 16) : (u & 0xFFFFu);
                    if (v > q) {
                        int p = atomicAdd(&s_na, 1);
                        s_selidx[p] = gi0 + h;
                    }
                }
            }
            __syncthreads();
            for (int i = 0; i < DH / 512; i++) {
                const unsigned u = smq[i * 256 + tid];
                const int gi0 = (i * 256 + tid) * 2;
#pragma unroll
                for (int h = 0; h < 2; h++) {
                    const unsigned v = h ? (u >> 16) : (u & 0xFFFFu);
                    if (v == q) {
                        int p = atomicAdd(&s_na, 1);
                        if (p < KSEL) s_selidx[p] = gi0 + h;
                    }
                }
            }
            __syncthreads();
            if (tid == 0) s_cnt = KSEL;
        }
        __syncthreads();
        const int scnt = s_cnt;
        for (int j = wid; j < scnt; j += 8) {
            const int fi = s_selidx[j];
            float d = dot16_warp(s_x, g_Whi + (long)fi * DM, lane);
            if (lane == 0) {
                d += benc[fi];
                s_selval[j] = fmaxf(d, 0.f);
            }
        }
    }

    // ---- fused decode (fp16 W_dec) ----
    __syncthreads();
    const int cnt = s_cnt;
    float4 acc = ((const float4*)bd)[tid];
#pragma unroll 4
    for (int j = 0; j < cnt; j++) {
        const float v = s_selval[j];
        const __half2* wrow = (const __half2*)(g_Wd16 + (long)s_selidx[j] * DM);
        const float2 f0 = __half22float2(wrow[tid * 2]);
        const float2 f1 = __half22float2(wrow[tid * 2 + 1]);
        acc.x = fmaf(v, f0.x, acc.x);
        acc.y = fmaf(v, f0.y, acc.y);
        acc.z = fmaf(v, f1.x, acc.z);
        acc.w = fmaf(v, f1.y, acc.w);
    }
    ((float4*)Y)[(long)row * (DM / 4) + tid] = acc;
}

// ============================================================
extern "C" void kernel_launch(void* const* d_in, const int* in_sizes, int n_in,
                              void* d_out, int out_size)
{
    const float* x     = (const float*)d_in[0];
    const float* W_enc = (const float*)d_in[1];
    const float* b_enc = (const float*)d_in[2];
    const float* W_dec = (const float*)d_in[3];
    const float* b_dec = (const float*)d_in[4];
    float* y = (float*)d_out;

    split_x_kernel<<<(TOK * DM) / (256 * 4), 256>>>(x);
    split_w_kernel<<<dim3(DH / 32, DM / 32), dim3(32, 8)>>>(W_enc);
    split_wd_kernel<<<((long)DH * DM) / (256 * 4), 256>>>(W_dec);

    cudaFuncSetAttribute(encode_mma_kernel,
                         cudaFuncAttributeMaxDynamicSharedMemorySize, SMEM_DYN);
    dim3 ge(DH / BN, TOK / BM);   // (128, 32)
    encode_mma_kernel<<<ge, 256, SMEM_DYN>>>(b_enc);

    cudaFuncSetAttribute(topk_decode_kernel,
                         cudaFuncAttributeMaxDynamicSharedMemorySize, DH * 2);
    topk_decode_kernel<<<TOK, 256, DH * 2>>>(x, b_enc, b_dec, y);
}